// round 2
// baseline (speedup 1.0000x reference)
#include <cuda_runtime.h>
#include <cuda_bf16.h>
#include <cuda_pipeline.h>
#include <cstdint>

// Problem constants
#define BH      128          // batch*heads
#define SEQ     1024
#define HD      64
#define TILE_Q  64           // query rows per block
#define CHUNK   128          // keys per smem chunk
#define NCHUNK  8            // SEQ / CHUNK
#define KPAD    72           // padded halves per smem row (bank-conflict-free)
#define INV_TEMP 0.125f      // 1 / 8.0
#define INV_DM1  (1.0f/1023.0f)

// Device scratch (static __device__ globals: the sanctioned no-alloc workaround).
// __align__(256): these are written as uint2 and read via 16B cp.async — the
// default 2B alignment of a bf16 array is NOT sufficient.
__device__ __align__(256) __nv_bfloat16 g_kb[(size_t)BH * SEQ * HD];
__device__ __align__(256) __nv_bfloat16 g_vb[(size_t)BH * SEQ * HD];
__device__ __align__(256) float         g_vsum[BH * HD];

// ---------------------------------------------------------------------------
// helpers
// ---------------------------------------------------------------------------
__device__ __forceinline__ uint32_t packbf(float x, float y) {
    __nv_bfloat162 h = __floats2bfloat162_rn(x, y);   // .x = x (low 16b), .y = y
    return *reinterpret_cast<uint32_t*>(&h);
}

__device__ __forceinline__ float2 unpackbf(uint32_t r) {
    __nv_bfloat162 h = *reinterpret_cast<__nv_bfloat162*>(&r);
    return __bfloat1622float2(h);
}

// mma.sync m16n8k16 row.col f32 += bf16 * bf16
__device__ __forceinline__ void mma_bf16(float (&d)[4], const uint32_t (&a)[4],
                                         uint32_t b0, uint32_t b1) {
    asm volatile(
        "mma.sync.aligned.m16n8k16.row.col.f32.bf16.bf16.f32 "
        "{%0,%1,%2,%3},{%4,%5,%6,%7},{%8,%9},{%0,%1,%2,%3};"
        : "+f"(d[0]), "+f"(d[1]), "+f"(d[2]), "+f"(d[3])
        : "r"(a[0]), "r"(a[1]), "r"(a[2]), "r"(a[3]), "r"(b0), "r"(b1));
}

// cooperative async copy of one 128-key x 64-half chunk into padded smem
__device__ __forceinline__ void load_chunk(const __nv_bfloat16* __restrict__ src,
                                           __nv_bfloat16* dstbase, int tid) {
#pragma unroll
    for (int i = 0; i < 4; i++) {
        int gi  = tid + i * 256;
        int row = gi >> 3;      // 0..127
        int c16 = gi & 7;       // 16B segment within row
        __pipeline_memcpy_async(dstbase + row * KPAD + c16 * 8,
                                src + row * HD + c16 * 8, 16);
    }
}

// ---------------------------------------------------------------------------
// kernel 1: fp32 -> bf16 conversion of K and V
// ---------------------------------------------------------------------------
__global__ void convert_kernel(const float* __restrict__ k, const float* __restrict__ v) {
    const unsigned N4 = (unsigned)(BH * SEQ * HD / 4);   // float4 count per tensor
    unsigned i = blockIdx.x * blockDim.x + threadIdx.x;
    const float4* src;
    uint2* dst;
    if (i < N4) {
        src = reinterpret_cast<const float4*>(k) + i;
        dst = reinterpret_cast<uint2*>(g_kb) + i;
    } else {
        unsigned j = i - N4;
        src = reinterpret_cast<const float4*>(v) + j;
        dst = reinterpret_cast<uint2*>(g_vb) + j;
    }
    float4 x = *src;
    uint2 o;
    o.x = packbf(x.x, x.y);
    o.y = packbf(x.z, x.w);
    *dst = o;
}

// ---------------------------------------------------------------------------
// kernel 2: column sums of V per (b,h):  g_vsum[bh][d] = sum_k v[bh][k][d]
// ---------------------------------------------------------------------------
__global__ void vsum_kernel(const float* __restrict__ v) {
    int bh = blockIdx.x;
    int d  = threadIdx.x;
    const float* p = v + (size_t)bh * SEQ * HD + d;
    float s = 0.f;
#pragma unroll 8
    for (int k = 0; k < SEQ; k++) s += p[k * HD];
    g_vsum[bh * HD + d] = s;
}

// ---------------------------------------------------------------------------
// kernel 3: fused attention
//   grid (SEQ/TILE_Q, BH), 256 threads = 8 warps = 4 query-groups x 2 key-halves
//   phase 1: S = (Q/8) K^T, E = exp(S) kept in registers (bf16), row sums
//   phase 2: P = E/sum; write attn' = (1-P)/1023; O += P V (mma)
//   epilogue: out = (vsum - O)/1023
// ---------------------------------------------------------------------------
__global__ __launch_bounds__(256, 1)
void attn_kernel(const float* __restrict__ q,
                 float* __restrict__ out,
                 float* __restrict__ attn) {
    __shared__ __align__(16) __nv_bfloat16 sKV[2][CHUNK][KPAD];   // 36.9 KB
    __shared__ float rs[4][16];

    const int bh  = blockIdx.y;
    const int q0  = blockIdx.x * TILE_Q;
    const int tid = threadIdx.x;
    const int warp = tid >> 5;
    const int lane = tid & 31;
    const int qg = warp >> 1;        // query group (16 rows each)
    const int w2 = warp & 1;         // which 64-key half of each chunk
    const int g  = lane >> 2;        // 0..7
    const int t  = lane & 3;         // 0..3

    if (tid < 64) ((float*)rs)[tid] = 0.f;

    // ---- Q a-fragments (load once from global, scale by 1/8, bf16) ----
    const int row_lo = q0 + qg * 16 + g;
    const float* qp = q + ((size_t)bh * SEQ + row_lo) * HD;
    uint32_t QA[4][4];
#pragma unroll
    for (int ks = 0; ks < 4; ks++) {
        float2 x0 = *reinterpret_cast<const float2*>(qp +            ks * 16 + 2 * t);
        float2 x1 = *reinterpret_cast<const float2*>(qp + 8 * HD +   ks * 16 + 2 * t);
        float2 x2 = *reinterpret_cast<const float2*>(qp +            ks * 16 + 8 + 2 * t);
        float2 x3 = *reinterpret_cast<const float2*>(qp + 8 * HD +   ks * 16 + 8 + 2 * t);
        QA[ks][0] = packbf(x0.x * INV_TEMP, x0.y * INV_TEMP);
        QA[ks][1] = packbf(x1.x * INV_TEMP, x1.y * INV_TEMP);
        QA[ks][2] = packbf(x2.x * INV_TEMP, x2.y * INV_TEMP);
        QA[ks][3] = packbf(x3.x * INV_TEMP, x3.y * INV_TEMP);
    }

    const __nv_bfloat16* Kbh = g_kb + (size_t)bh * SEQ * HD;
    const __nv_bfloat16* Vbh = g_vb + (size_t)bh * SEQ * HD;

    uint32_t E[NCHUNK][8][2];        // exp(scores), bf16 packed; 128 regs
    float rsum_lo = 0.f, rsum_hi = 0.f;

    // ======================= phase 1: QK^T + exp =======================
    load_chunk(Kbh, &sKV[0][0][0], tid);
    __pipeline_commit();
#pragma unroll
    for (int c = 0; c < NCHUNK; c++) {
        if (c + 1 < NCHUNK) {
            load_chunk(Kbh + (size_t)(c + 1) * CHUNK * HD, &sKV[(c + 1) & 1][0][0], tid);
            __pipeline_commit();
            __pipeline_wait_prior(1);
        } else {
            __pipeline_wait_prior(0);
        }
        __syncthreads();
        const __nv_bfloat16 (*buf)[KPAD] = sKV[c & 1];

        float acc[8][4];
#pragma unroll
        for (int nt = 0; nt < 8; nt++) {
            acc[nt][0] = acc[nt][1] = acc[nt][2] = acc[nt][3] = 0.f;
        }
#pragma unroll
        for (int ks = 0; ks < 4; ks++) {
#pragma unroll
            for (int nt = 0; nt < 8; nt++) {
                const __nv_bfloat16* kr = &buf[w2 * 64 + nt * 8 + g][ks * 16 + 2 * t];
                uint32_t b0 = *reinterpret_cast<const uint32_t*>(kr);
                uint32_t b1 = *reinterpret_cast<const uint32_t*>(kr + 8);
                mma_bf16(acc[nt], QA[ks], b0, b1);
            }
        }
#pragma unroll
        for (int nt = 0; nt < 8; nt++) {
            float e0 = __expf(acc[nt][0]);
            float e1 = __expf(acc[nt][1]);
            float e2 = __expf(acc[nt][2]);
            float e3 = __expf(acc[nt][3]);
            rsum_lo += e0 + e1;
            rsum_hi += e2 + e3;
            E[c][nt][0] = packbf(e0, e1);   // row g
            E[c][nt][1] = packbf(e2, e3);   // row g+8
        }
        __syncthreads();
    }

    // ---- row-sum reduction (4 lanes share a row, then 2 warps per group) ----
    rsum_lo += __shfl_xor_sync(0xffffffffu, rsum_lo, 1);
    rsum_lo += __shfl_xor_sync(0xffffffffu, rsum_lo, 2);
    rsum_hi += __shfl_xor_sync(0xffffffffu, rsum_hi, 1);
    rsum_hi += __shfl_xor_sync(0xffffffffu, rsum_hi, 2);
    if (t == 0) {
        atomicAdd(&rs[qg][g],     rsum_lo);
        atomicAdd(&rs[qg][g + 8], rsum_hi);
    }
    __syncthreads();
    const float inv_lo = 1.f / rs[qg][g];
    const float inv_hi = 1.f / rs[qg][g + 8];

    // ======================= phase 2: attn write + P@V =======================
    float Oacc[8][4];
#pragma unroll
    for (int nt = 0; nt < 8; nt++) {
        Oacc[nt][0] = Oacc[nt][1] = Oacc[nt][2] = Oacc[nt][3] = 0.f;
    }

    float* attn_lo = attn + ((size_t)bh * SEQ + row_lo) * SEQ;
    float* attn_hi = attn_lo + (size_t)8 * SEQ;

    load_chunk(Vbh, &sKV[0][0][0], tid);
    __pipeline_commit();
#pragma unroll
    for (int c = 0; c < NCHUNK; c++) {
        if (c + 1 < NCHUNK) {
            load_chunk(Vbh + (size_t)(c + 1) * CHUNK * HD, &sKV[(c + 1) & 1][0][0], tid);
            __pipeline_commit();
            __pipeline_wait_prior(1);
        } else {
            __pipeline_wait_prior(0);
        }
        __syncthreads();
        const __nv_bfloat16 (*buf)[KPAD] = sKV[c & 1];

#pragma unroll
        for (int ks = 0; ks < 4; ks++) {
            // build P a-fragments from stored E and per-row inverse sums
            float2 eA0 = unpackbf(E[c][2 * ks][0]);
            float2 eA1 = unpackbf(E[c][2 * ks][1]);
            float2 eB0 = unpackbf(E[c][2 * ks + 1][0]);
            float2 eB1 = unpackbf(E[c][2 * ks + 1][1]);
            float p00 = eA0.x * inv_lo, p01 = eA0.y * inv_lo;
            float p10 = eA1.x * inv_hi, p11 = eA1.y * inv_hi;
            float p20 = eB0.x * inv_lo, p21 = eB0.y * inv_lo;
            float p30 = eB1.x * inv_hi, p31 = eB1.y * inv_hi;
            uint32_t aa[4];
            aa[0] = packbf(p00, p01);
            aa[1] = packbf(p10, p11);
            aa[2] = packbf(p20, p21);
            aa[3] = packbf(p30, p31);

            // streaming attn stores: attn' = (1 - P)/1023
            int kb = c * CHUNK + w2 * 64 + ks * 16;
            __stcs(reinterpret_cast<float2*>(attn_lo + kb + 2 * t),
                   make_float2((1.f - p00) * INV_DM1, (1.f - p01) * INV_DM1));
            __stcs(reinterpret_cast<float2*>(attn_hi + kb + 2 * t),
                   make_float2((1.f - p10) * INV_DM1, (1.f - p11) * INV_DM1));
            __stcs(reinterpret_cast<float2*>(attn_lo + kb + 8 + 2 * t),
                   make_float2((1.f - p20) * INV_DM1, (1.f - p21) * INV_DM1));
            __stcs(reinterpret_cast<float2*>(attn_hi + kb + 8 + 2 * t),
                   make_float2((1.f - p30) * INV_DM1, (1.f - p31) * INV_DM1));

            // V b-fragments via ldmatrix.trans, accumulate O += P V
            int vrow_base = w2 * 64 + ks * 16;
            int quad = lane >> 3, rq = lane & 7;
#pragma unroll
            for (int dp = 0; dp < 4; dp++) {
                const __nv_bfloat16* vp =
                    &buf[vrow_base + (quad & 1) * 8 + rq][dp * 16 + (quad >> 1) * 8];
                uint32_t sa = (uint32_t)__cvta_generic_to_shared(vp);
                uint32_t b0, b1, b2, b3;
                asm volatile(
                    "ldmatrix.sync.aligned.m8n8.x4.trans.shared.b16 {%0,%1,%2,%3},[%4];"
                    : "=r"(b0), "=r"(b1), "=r"(b2), "=r"(b3)
                    : "r"(sa));
                mma_bf16(Oacc[2 * dp],     aa, b0, b1);
                mma_bf16(Oacc[2 * dp + 1], aa, b2, b3);
            }
        }
        __syncthreads();
    }

    // ======================= epilogue: reduce O across warp pairs =======================
    float (*Ored)[HD] = reinterpret_cast<float (*)[HD]>(&sKV[0][0][0]);  // 16 KB overlay
    if (w2 == 0) {
#pragma unroll
        for (int nt = 0; nt < 8; nt++) {
            *reinterpret_cast<float2*>(&Ored[qg * 16 + g][nt * 8 + 2 * t]) =
                make_float2(Oacc[nt][0], Oacc[nt][1]);
            *reinterpret_cast<float2*>(&Ored[qg * 16 + g + 8][nt * 8 + 2 * t]) =
                make_float2(Oacc[nt][2], Oacc[nt][3]);
        }
    }
    __syncthreads();
    if (w2 == 1) {
#pragma unroll
        for (int nt = 0; nt < 8; nt++) {
            float2* p0 = reinterpret_cast<float2*>(&Ored[qg * 16 + g][nt * 8 + 2 * t]);
            float2 v0 = *p0;
            v0.x += Oacc[nt][0]; v0.y += Oacc[nt][1];
            *p0 = v0;
            float2* p1 = reinterpret_cast<float2*>(&Ored[qg * 16 + g + 8][nt * 8 + 2 * t]);
            float2 v1 = *p1;
            v1.x += Oacc[nt][2]; v1.y += Oacc[nt][3];
            *p1 = v1;
        }
    }
    __syncthreads();

    // out = (vsum - O) / 1023
    float* outb = out + ((size_t)bh * SEQ + q0) * HD;
    for (int idx = tid; idx < TILE_Q * HD; idx += 256) {
        int r = idx >> 6, d = idx & 63;
        outb[r * HD + d] = (g_vsum[bh * HD + d] - Ored[r][d]) * INV_DM1;
    }
}

// ---------------------------------------------------------------------------
// launch
// ---------------------------------------------------------------------------
extern "C" void kernel_launch(void* const* d_in, const int* in_sizes, int n_in,
                              void* d_out, int out_size) {
    (void)in_sizes; (void)n_in; (void)out_size;
    const float* q = (const float*)d_in[0];
    const float* k = (const float*)d_in[1];
    const float* v = (const float*)d_in[2];
    float* out  = (float*)d_out;
    float* attn = out + (size_t)BH * SEQ * HD;   // tuple order: (out, attn)

    const int n4_total = 2 * (BH * SEQ * HD / 4);           // K + V float4 count
    convert_kernel<<<n4_total / 256, 256>>>(k, v);
    vsum_kernel<<<BH, HD>>>(v);
    attn_kernel<<<dim3(SEQ / TILE_Q, BH), 256>>>(q, out, attn);
}

// round 3
// speedup vs baseline: 1.5594x; 1.5594x over previous
#include <cuda_runtime.h>
#include <cuda_bf16.h>
#include <cuda_pipeline.h>
#include <cstdint>

// Problem constants
#define BH      128          // batch*heads
#define SEQ     1024
#define HD      64
#define TILE_Q  64           // query rows per block
#define CHUNK   128          // keys per smem chunk
#define NCHUNK  8            // SEQ / CHUNK
#define KPAD    72           // padded halves per smem row (conflict-free: 144B stride)
#define INV_TEMP 0.125f      // 1 / 8.0
#define INV_DM1  (1.0f/1023.0f)

// Device scratch (sanctioned no-alloc workaround). __align__(256): written as
// uint2 / read via 16B cp.async.
__device__ __align__(256) __nv_bfloat16 g_kb[(size_t)BH * SEQ * HD];
__device__ __align__(256) __nv_bfloat16 g_vb[(size_t)BH * SEQ * HD];
__device__ __align__(256) float         g_vsum[BH * HD];
__device__ __align__(256) float         g_rinv[BH * SEQ];   // 1 / softmax row sum

// ---------------------------------------------------------------------------
// helpers
// ---------------------------------------------------------------------------
__device__ __forceinline__ uint32_t packbf(float x, float y) {
    __nv_bfloat162 h = __floats2bfloat162_rn(x, y);
    return *reinterpret_cast<uint32_t*>(&h);
}

// mma.sync m16n8k16 row.col f32 += bf16 * bf16
__device__ __forceinline__ void mma_bf16(float (&d)[4], const uint32_t (&a)[4],
                                         uint32_t b0, uint32_t b1) {
    asm volatile(
        "mma.sync.aligned.m16n8k16.row.col.f32.bf16.bf16.f32 "
        "{%0,%1,%2,%3},{%4,%5,%6,%7},{%8,%9},{%0,%1,%2,%3};"
        : "+f"(d[0]), "+f"(d[1]), "+f"(d[2]), "+f"(d[3])
        : "r"(a[0]), "r"(a[1]), "r"(a[2]), "r"(a[3]), "r"(b0), "r"(b1));
}

__device__ __forceinline__ void ldmatrix_x4(uint32_t& r0, uint32_t& r1,
                                            uint32_t& r2, uint32_t& r3,
                                            const void* p) {
    uint32_t sa = (uint32_t)__cvta_generic_to_shared(p);
    asm volatile("ldmatrix.sync.aligned.m8n8.x4.shared.b16 {%0,%1,%2,%3},[%4];"
                 : "=r"(r0), "=r"(r1), "=r"(r2), "=r"(r3) : "r"(sa));
}

__device__ __forceinline__ void ldmatrix_x4_trans(uint32_t& r0, uint32_t& r1,
                                                  uint32_t& r2, uint32_t& r3,
                                                  const void* p) {
    uint32_t sa = (uint32_t)__cvta_generic_to_shared(p);
    asm volatile("ldmatrix.sync.aligned.m8n8.x4.trans.shared.b16 {%0,%1,%2,%3},[%4];"
                 : "=r"(r0), "=r"(r1), "=r"(r2), "=r"(r3) : "r"(sa));
}

// cooperative async copy of one 128-key x 64-half chunk into padded smem
__device__ __forceinline__ void load_chunk(const __nv_bfloat16* __restrict__ src,
                                           __nv_bfloat16* dstbase, int tid) {
#pragma unroll
    for (int i = 0; i < 4; i++) {
        int gi  = tid + i * 256;
        int row = gi >> 3;      // 0..127
        int c16 = gi & 7;       // 16B segment within row
        __pipeline_memcpy_async(dstbase + row * KPAD + c16 * 8,
                                src + row * HD + c16 * 8, 16);
    }
}

// Q a-fragments: 16 rows per query-group, scaled by 1/8, packed bf16
__device__ __forceinline__ void load_q_frags(const float* __restrict__ qp,
                                             uint32_t (&QA)[4][4], int t) {
#pragma unroll
    for (int ks = 0; ks < 4; ks++) {
        float2 x0 = *reinterpret_cast<const float2*>(qp +          ks * 16 +     2 * t);
        float2 x1 = *reinterpret_cast<const float2*>(qp + 8 * HD + ks * 16 +     2 * t);
        float2 x2 = *reinterpret_cast<const float2*>(qp +          ks * 16 + 8 + 2 * t);
        float2 x3 = *reinterpret_cast<const float2*>(qp + 8 * HD + ks * 16 + 8 + 2 * t);
        QA[ks][0] = packbf(x0.x * INV_TEMP, x0.y * INV_TEMP);
        QA[ks][1] = packbf(x1.x * INV_TEMP, x1.y * INV_TEMP);
        QA[ks][2] = packbf(x2.x * INV_TEMP, x2.y * INV_TEMP);
        QA[ks][3] = packbf(x3.x * INV_TEMP, x3.y * INV_TEMP);
    }
}

// ---------------------------------------------------------------------------
// kernel 1: fp32 -> bf16 conversion of K and V
// ---------------------------------------------------------------------------
__global__ void convert_kernel(const float* __restrict__ k, const float* __restrict__ v) {
    const unsigned N4 = (unsigned)(BH * SEQ * HD / 4);
    unsigned i = blockIdx.x * blockDim.x + threadIdx.x;
    const float4* src;
    uint2* dst;
    if (i < N4) {
        src = reinterpret_cast<const float4*>(k) + i;
        dst = reinterpret_cast<uint2*>(g_kb) + i;
    } else {
        unsigned j = i - N4;
        src = reinterpret_cast<const float4*>(v) + j;
        dst = reinterpret_cast<uint2*>(g_vb) + j;
    }
    float4 x = *src;
    uint2 o;
    o.x = packbf(x.x, x.y);
    o.y = packbf(x.z, x.w);
    *dst = o;
}

// ---------------------------------------------------------------------------
// kernel 2: column sums of V per (b,h)
// ---------------------------------------------------------------------------
__global__ void vsum_kernel(const float* __restrict__ v) {
    __shared__ float part[4][HD];
    int bh = blockIdx.x;
    int tid = threadIdx.x;                 // 256
    int d = tid & 63, seg = tid >> 6;      // 4 segments of 256 keys
    const float* p = v + (size_t)bh * SEQ * HD + (size_t)seg * 256 * HD + d;
    float s = 0.f;
#pragma unroll 8
    for (int k = 0; k < 256; k++) s += p[k * HD];
    part[seg][d] = s;
    __syncthreads();
    if (tid < HD)
        g_vsum[bh * HD + tid] = part[0][tid] + part[1][tid] + part[2][tid] + part[3][tid];
}

// ---------------------------------------------------------------------------
// kernel 3: softmax row sums -> g_rinv = 1/rowsum
//   grid (SEQ/TILE_Q, BH), 256 thr = 4 query-groups x 2 key-halves
// ---------------------------------------------------------------------------
__global__ __launch_bounds__(256, 2)
void rowsum_kernel(const float* __restrict__ q) {
    __shared__ __align__(16) __nv_bfloat16 sK[2][CHUNK][KPAD];   // 36.9 KB
    __shared__ float rs[4][16];

    const int bh  = blockIdx.y;
    const int q0  = blockIdx.x * TILE_Q;
    const int tid = threadIdx.x;
    const int warp = tid >> 5, lane = tid & 31;
    const int qg = warp >> 1, w2 = warp & 1;
    const int g  = lane >> 2, t = lane & 3;
    const int m  = lane >> 3, r = lane & 7;      // ldmatrix addressing

    if (tid < 64) ((float*)rs)[tid] = 0.f;

    const int row_lo = q0 + qg * 16 + g;
    uint32_t QA[4][4];
    load_q_frags(q + ((size_t)bh * SEQ + row_lo) * HD, QA, t);

    const __nv_bfloat16* Kbh = g_kb + (size_t)bh * SEQ * HD;

    float rsum_lo = 0.f, rsum_hi = 0.f;

    load_chunk(Kbh, &sK[0][0][0], tid);
    __pipeline_commit();
#pragma unroll 2
    for (int c = 0; c < NCHUNK; c++) {
        if (c + 1 < NCHUNK) {
            load_chunk(Kbh + (size_t)(c + 1) * CHUNK * HD, &sK[(c + 1) & 1][0][0], tid);
            __pipeline_commit();
            __pipeline_wait_prior(1);
        } else {
            __pipeline_wait_prior(0);
        }
        __syncthreads();
        const __nv_bfloat16 (*bK)[KPAD] = sK[c & 1];

#pragma unroll
        for (int ks2 = 0; ks2 < 4; ks2++) {          // 16-key subgroup
            float Sacc[2][4];
            Sacc[0][0]=Sacc[0][1]=Sacc[0][2]=Sacc[0][3]=0.f;
            Sacc[1][0]=Sacc[1][1]=Sacc[1][2]=Sacc[1][3]=0.f;
#pragma unroll
            for (int ks = 0; ks < 4; ks++) {
                uint32_t f0,f1,f2,f3;
                ldmatrix_x4(f0,f1,f2,f3,
                    &bK[w2*64 + ks2*16 + (m>>1)*8 + r][ks*16 + (m&1)*8]);
                mma_bf16(Sacc[0], QA[ks], f0, f1);
                mma_bf16(Sacc[1], QA[ks], f2, f3);
            }
            rsum_lo += __expf(Sacc[0][0]) + __expf(Sacc[0][1])
                     + __expf(Sacc[1][0]) + __expf(Sacc[1][1]);
            rsum_hi += __expf(Sacc[0][2]) + __expf(Sacc[0][3])
                     + __expf(Sacc[1][2]) + __expf(Sacc[1][3]);
        }
        __syncthreads();
    }

    rsum_lo += __shfl_xor_sync(0xffffffffu, rsum_lo, 1);
    rsum_lo += __shfl_xor_sync(0xffffffffu, rsum_lo, 2);
    rsum_hi += __shfl_xor_sync(0xffffffffu, rsum_hi, 1);
    rsum_hi += __shfl_xor_sync(0xffffffffu, rsum_hi, 2);
    if (t == 0) {
        atomicAdd(&rs[qg][g],     rsum_lo);
        atomicAdd(&rs[qg][g + 8], rsum_hi);
    }
    __syncthreads();
    if (tid < 64) {
        int qq = tid >> 4, rr = tid & 15;
        g_rinv[(size_t)bh * SEQ + q0 + qq * 16 + rr] = 1.f / rs[qq][rr];
    }
}

// ---------------------------------------------------------------------------
// kernel 4: single-pass attention using precomputed 1/rowsum
//   per 16-key subgroup: recompute S (8 mma), P = exp(S)*rinv,
//   attn' = (1-P)/1023 streamed out, O += P V (8 mma)
// ---------------------------------------------------------------------------
#define ATTN_SMEM (4 * CHUNK * KPAD * 2)   // sK[2] + sV[2] = 73728 B

__global__ __launch_bounds__(256, 2)
void attn2_kernel(const float* __restrict__ q,
                  float* __restrict__ out,
                  float* __restrict__ attn) {
    extern __shared__ __align__(16) char dynsmem[];
    __nv_bfloat16 (*sK)[CHUNK][KPAD] =
        reinterpret_cast<__nv_bfloat16 (*)[CHUNK][KPAD]>(dynsmem);
    __nv_bfloat16 (*sV)[CHUNK][KPAD] =
        reinterpret_cast<__nv_bfloat16 (*)[CHUNK][KPAD]>(dynsmem + 2 * CHUNK * KPAD * 2);

    const int bh  = blockIdx.y;
    const int q0  = blockIdx.x * TILE_Q;
    const int tid = threadIdx.x;
    const int warp = tid >> 5, lane = tid & 31;
    const int qg = warp >> 1, w2 = warp & 1;
    const int g  = lane >> 2, t = lane & 3;
    const int m  = lane >> 3, r = lane & 7;

    const int row_lo = q0 + qg * 16 + g;
    uint32_t QA[4][4];
    load_q_frags(q + ((size_t)bh * SEQ + row_lo) * HD, QA, t);

    const float inv_lo = __ldg(&g_rinv[(size_t)bh * SEQ + row_lo]);
    const float inv_hi = __ldg(&g_rinv[(size_t)bh * SEQ + row_lo + 8]);

    const __nv_bfloat16* Kbh = g_kb + (size_t)bh * SEQ * HD;
    const __nv_bfloat16* Vbh = g_vb + (size_t)bh * SEQ * HD;

    float Oacc[8][4];
#pragma unroll
    for (int nt = 0; nt < 8; nt++)
        Oacc[nt][0] = Oacc[nt][1] = Oacc[nt][2] = Oacc[nt][3] = 0.f;

    float* attn_lo = attn + ((size_t)bh * SEQ + row_lo) * SEQ;
    float* attn_hi = attn_lo + (size_t)8 * SEQ;

    load_chunk(Kbh, &sK[0][0][0], tid);
    load_chunk(Vbh, &sV[0][0][0], tid);
    __pipeline_commit();
#pragma unroll 2
    for (int c = 0; c < NCHUNK; c++) {
        if (c + 1 < NCHUNK) {
            load_chunk(Kbh + (size_t)(c + 1) * CHUNK * HD, &sK[(c + 1) & 1][0][0], tid);
            load_chunk(Vbh + (size_t)(c + 1) * CHUNK * HD, &sV[(c + 1) & 1][0][0], tid);
            __pipeline_commit();
            __pipeline_wait_prior(1);
        } else {
            __pipeline_wait_prior(0);
        }
        __syncthreads();
        const __nv_bfloat16 (*bK)[KPAD] = sK[c & 1];
        const __nv_bfloat16 (*bV)[KPAD] = sV[c & 1];

#pragma unroll
        for (int ks2 = 0; ks2 < 4; ks2++) {          // 16-key subgroup
            // ---- recompute S for these 16 keys ----
            float Sacc[2][4];
            Sacc[0][0]=Sacc[0][1]=Sacc[0][2]=Sacc[0][3]=0.f;
            Sacc[1][0]=Sacc[1][1]=Sacc[1][2]=Sacc[1][3]=0.f;
#pragma unroll
            for (int ks = 0; ks < 4; ks++) {
                uint32_t f0,f1,f2,f3;
                ldmatrix_x4(f0,f1,f2,f3,
                    &bK[w2*64 + ks2*16 + (m>>1)*8 + r][ks*16 + (m&1)*8]);
                mma_bf16(Sacc[0], QA[ks], f0, f1);
                mma_bf16(Sacc[1], QA[ks], f2, f3);
            }
            // ---- P = exp(S) * rinv ----
            float p00 = __expf(Sacc[0][0]) * inv_lo, p01 = __expf(Sacc[0][1]) * inv_lo;
            float p10 = __expf(Sacc[0][2]) * inv_hi, p11 = __expf(Sacc[0][3]) * inv_hi;
            float p20 = __expf(Sacc[1][0]) * inv_lo, p21 = __expf(Sacc[1][1]) * inv_lo;
            float p30 = __expf(Sacc[1][2]) * inv_hi, p31 = __expf(Sacc[1][3]) * inv_hi;

            uint32_t aa[4];
            aa[0] = packbf(p00, p01);
            aa[1] = packbf(p10, p11);
            aa[2] = packbf(p20, p21);
            aa[3] = packbf(p30, p31);

            // ---- streaming attn stores: attn' = (1 - P)/1023 ----
            int kb = c * CHUNK + w2 * 64 + ks2 * 16;
            __stcs(reinterpret_cast<float2*>(attn_lo + kb + 2 * t),
                   make_float2((1.f - p00) * INV_DM1, (1.f - p01) * INV_DM1));
            __stcs(reinterpret_cast<float2*>(attn_hi + kb + 2 * t),
                   make_float2((1.f - p10) * INV_DM1, (1.f - p11) * INV_DM1));
            __stcs(reinterpret_cast<float2*>(attn_lo + kb + 8 + 2 * t),
                   make_float2((1.f - p20) * INV_DM1, (1.f - p21) * INV_DM1));
            __stcs(reinterpret_cast<float2*>(attn_hi + kb + 8 + 2 * t),
                   make_float2((1.f - p30) * INV_DM1, (1.f - p31) * INV_DM1));

            // ---- O += P V ----
            int vrow_base = w2 * 64 + ks2 * 16;
            int quad = lane >> 3, rq = lane & 7;
#pragma unroll
            for (int dp = 0; dp < 4; dp++) {
                uint32_t b0, b1, b2, b3;
                ldmatrix_x4_trans(b0, b1, b2, b3,
                    &bV[vrow_base + (quad & 1) * 8 + rq][dp * 16 + (quad >> 1) * 8]);
                mma_bf16(Oacc[2 * dp],     aa, b0, b1);
                mma_bf16(Oacc[2 * dp + 1], aa, b2, b3);
            }
        }
        __syncthreads();
    }

    // ---- epilogue: reduce O across warp pairs, out = (vsum - O)/1023 ----
    float (*Ored)[HD] = reinterpret_cast<float (*)[HD]>(dynsmem);   // 16 KB overlay
    if (w2 == 0) {
#pragma unroll
        for (int nt = 0; nt < 8; nt++) {
            *reinterpret_cast<float2*>(&Ored[qg * 16 + g][nt * 8 + 2 * t]) =
                make_float2(Oacc[nt][0], Oacc[nt][1]);
            *reinterpret_cast<float2*>(&Ored[qg * 16 + g + 8][nt * 8 + 2 * t]) =
                make_float2(Oacc[nt][2], Oacc[nt][3]);
        }
    }
    __syncthreads();
    if (w2 == 1) {
#pragma unroll
        for (int nt = 0; nt < 8; nt++) {
            float2* p0 = reinterpret_cast<float2*>(&Ored[qg * 16 + g][nt * 8 + 2 * t]);
            float2 v0 = *p0;
            v0.x += Oacc[nt][0]; v0.y += Oacc[nt][1];
            *p0 = v0;
            float2* p1 = reinterpret_cast<float2*>(&Ored[qg * 16 + g + 8][nt * 8 + 2 * t]);
            float2 v1 = *p1;
            v1.x += Oacc[nt][2]; v1.y += Oacc[nt][3];
            *p1 = v1;
        }
    }
    __syncthreads();

    float* outb = out + ((size_t)bh * SEQ + q0) * HD;
    for (int idx = tid; idx < TILE_Q * HD; idx += 256) {
        int rr = idx >> 6, d = idx & 63;
        outb[rr * HD + d] = (g_vsum[bh * HD + d] - Ored[rr][d]) * INV_DM1;
    }
}

// ---------------------------------------------------------------------------
// launch
// ---------------------------------------------------------------------------
extern "C" void kernel_launch(void* const* d_in, const int* in_sizes, int n_in,
                              void* d_out, int out_size) {
    (void)in_sizes; (void)n_in; (void)out_size;
    const float* q = (const float*)d_in[0];
    const float* k = (const float*)d_in[1];
    const float* v = (const float*)d_in[2];
    float* out  = (float*)d_out;
    float* attn = out + (size_t)BH * SEQ * HD;   // tuple order: (out, attn)

    // opt-in to >48KB dynamic smem (attribute set is idempotent & capture-safe)
    cudaFuncSetAttribute(attn2_kernel,
                         cudaFuncAttributeMaxDynamicSharedMemorySize, ATTN_SMEM);

    const int n4_total = 2 * (BH * SEQ * HD / 4);
    convert_kernel<<<n4_total / 256, 256>>>(k, v);
    vsum_kernel<<<BH, 256>>>(v);
    rowsum_kernel<<<dim3(SEQ / TILE_Q, BH), 256>>>(q);
    attn2_kernel<<<dim3(SEQ / TILE_Q, BH), 256, ATTN_SMEM>>>(q, out, attn);
}

// round 4
// speedup vs baseline: 1.5616x; 1.0014x over previous
#include <cuda_runtime.h>
#include <cuda_bf16.h>
#include <cuda_pipeline.h>
#include <cstdint>

// Problem constants
#define BH      128          // batch*heads
#define SEQ     1024
#define HD      64
#define TILE_Q  64           // query rows per block
#define CHUNK   128          // keys per smem chunk
#define NCHUNK  8            // SEQ / CHUNK
#define KPAD    72           // padded halves per smem row (conflict-free: 144B stride)
#define INV_TEMP 0.125f      // 1 / 8.0
#define INV_DM1  (1.0f/1023.0f)

// Device scratch (sanctioned no-alloc workaround). __align__(256): written as
// uint2 / read via 16B cp.async.
__device__ __align__(256) __nv_bfloat16 g_kb[(size_t)BH * SEQ * HD];
__device__ __align__(256) __nv_bfloat16 g_vb[(size_t)BH * SEQ * HD];
__device__ __align__(256) float         g_vsum[BH * HD];
__device__ __align__(256) float         g_rinv[BH * SEQ];   // 1 / softmax row sum

// ---------------------------------------------------------------------------
// helpers
// ---------------------------------------------------------------------------
__device__ __forceinline__ uint32_t packbf(float x, float y) {
    __nv_bfloat162 h = __floats2bfloat162_rn(x, y);
    return *reinterpret_cast<uint32_t*>(&h);
}

// mma.sync m16n8k16 row.col f32 += bf16 * bf16
__device__ __forceinline__ void mma_bf16(float (&d)[4], const uint32_t (&a)[4],
                                         uint32_t b0, uint32_t b1) {
    asm volatile(
        "mma.sync.aligned.m16n8k16.row.col.f32.bf16.bf16.f32 "
        "{%0,%1,%2,%3},{%4,%5,%6,%7},{%8,%9},{%0,%1,%2,%3};"
        : "+f"(d[0]), "+f"(d[1]), "+f"(d[2]), "+f"(d[3])
        : "r"(a[0]), "r"(a[1]), "r"(a[2]), "r"(a[3]), "r"(b0), "r"(b1));
}

__device__ __forceinline__ void ldmatrix_x4(uint32_t& r0, uint32_t& r1,
                                            uint32_t& r2, uint32_t& r3,
                                            const void* p) {
    uint32_t sa = (uint32_t)__cvta_generic_to_shared(p);
    asm volatile("ldmatrix.sync.aligned.m8n8.x4.shared.b16 {%0,%1,%2,%3},[%4];"
                 : "=r"(r0), "=r"(r1), "=r"(r2), "=r"(r3) : "r"(sa));
}

__device__ __forceinline__ void ldmatrix_x4_trans(uint32_t& r0, uint32_t& r1,
                                                  uint32_t& r2, uint32_t& r3,
                                                  const void* p) {
    uint32_t sa = (uint32_t)__cvta_generic_to_shared(p);
    asm volatile("ldmatrix.sync.aligned.m8n8.x4.trans.shared.b16 {%0,%1,%2,%3},[%4];"
                 : "=r"(r0), "=r"(r1), "=r"(r2), "=r"(r3) : "r"(sa));
}

// cooperative async copy of one 128-key x 64-half chunk into padded smem
__device__ __forceinline__ void load_chunk(const __nv_bfloat16* __restrict__ src,
                                           __nv_bfloat16* dstbase, int tid) {
#pragma unroll
    for (int i = 0; i < 4; i++) {
        int gi  = tid + i * 256;
        int row = gi >> 3;      // 0..127
        int c16 = gi & 7;       // 16B segment within row
        __pipeline_memcpy_async(dstbase + row * KPAD + c16 * 8,
                                src + row * HD + c16 * 8, 16);
    }
}

// Q a-fragments: 16 rows per query-group, scaled by 1/8, packed bf16
__device__ __forceinline__ void load_q_frags(const float* __restrict__ qp,
                                             uint32_t (&QA)[4][4], int t) {
#pragma unroll
    for (int ks = 0; ks < 4; ks++) {
        float2 x0 = *reinterpret_cast<const float2*>(qp +          ks * 16 +     2 * t);
        float2 x1 = *reinterpret_cast<const float2*>(qp + 8 * HD + ks * 16 +     2 * t);
        float2 x2 = *reinterpret_cast<const float2*>(qp +          ks * 16 + 8 + 2 * t);
        float2 x3 = *reinterpret_cast<const float2*>(qp + 8 * HD + ks * 16 + 8 + 2 * t);
        QA[ks][0] = packbf(x0.x * INV_TEMP, x0.y * INV_TEMP);
        QA[ks][1] = packbf(x1.x * INV_TEMP, x1.y * INV_TEMP);
        QA[ks][2] = packbf(x2.x * INV_TEMP, x2.y * INV_TEMP);
        QA[ks][3] = packbf(x3.x * INV_TEMP, x3.y * INV_TEMP);
    }
}

// ---------------------------------------------------------------------------
// kernel 1: fp32 -> bf16 conversion of K and V
// ---------------------------------------------------------------------------
__global__ void convert_kernel(const float* __restrict__ k, const float* __restrict__ v) {
    const unsigned N4 = (unsigned)(BH * SEQ * HD / 4);
    unsigned i = blockIdx.x * blockDim.x + threadIdx.x;
    const float4* src;
    uint2* dst;
    if (i < N4) {
        src = reinterpret_cast<const float4*>(k) + i;
        dst = reinterpret_cast<uint2*>(g_kb) + i;
    } else {
        unsigned j = i - N4;
        src = reinterpret_cast<const float4*>(v) + j;
        dst = reinterpret_cast<uint2*>(g_vb) + j;
    }
    float4 x = *src;
    uint2 o;
    o.x = packbf(x.x, x.y);
    o.y = packbf(x.z, x.w);
    *dst = o;
}

// ---------------------------------------------------------------------------
// kernel 2: column sums of V per (b,h)
// ---------------------------------------------------------------------------
__global__ void vsum_kernel(const float* __restrict__ v) {
    __shared__ float part[4][HD];
    int bh = blockIdx.x;
    int tid = threadIdx.x;                 // 256
    int d = tid & 63, seg = tid >> 6;      // 4 segments of 256 keys
    const float* p = v + (size_t)bh * SEQ * HD + (size_t)seg * 256 * HD + d;
    float s = 0.f;
#pragma unroll 8
    for (int k = 0; k < 256; k++) s += p[k * HD];
    part[seg][d] = s;
    __syncthreads();
    if (tid < HD)
        g_vsum[bh * HD + tid] = part[0][tid] + part[1][tid] + part[2][tid] + part[3][tid];
}

// ---------------------------------------------------------------------------
// kernel 3: softmax row sums -> g_rinv = 1/rowsum
//   grid (SEQ/TILE_Q, BH), 256 thr = 4 query-groups x 2 key-halves
// ---------------------------------------------------------------------------
__global__ __launch_bounds__(256, 2)
void rowsum_kernel(const float* __restrict__ q) {
    __shared__ __align__(16) __nv_bfloat16 sK[2][CHUNK][KPAD];   // 36.9 KB
    __shared__ float rs[4][16];

    const int bh  = blockIdx.y;
    const int q0  = blockIdx.x * TILE_Q;
    const int tid = threadIdx.x;
    const int warp = tid >> 5, lane = tid & 31;
    const int qg = warp >> 1, w2 = warp & 1;
    const int g  = lane >> 2, t = lane & 3;
    const int m  = lane >> 3, r = lane & 7;      // ldmatrix addressing

    if (tid < 64) ((float*)rs)[tid] = 0.f;

    const int row_lo = q0 + qg * 16 + g;
    uint32_t QA[4][4];
    load_q_frags(q + ((size_t)bh * SEQ + row_lo) * HD, QA, t);

    const __nv_bfloat16* Kbh = g_kb + (size_t)bh * SEQ * HD;

    float rsum_lo = 0.f, rsum_hi = 0.f;

    load_chunk(Kbh, &sK[0][0][0], tid);
    __pipeline_commit();
#pragma unroll 2
    for (int c = 0; c < NCHUNK; c++) {
        if (c + 1 < NCHUNK) {
            load_chunk(Kbh + (size_t)(c + 1) * CHUNK * HD, &sK[(c + 1) & 1][0][0], tid);
            __pipeline_commit();
            __pipeline_wait_prior(1);
        } else {
            __pipeline_wait_prior(0);
        }
        __syncthreads();
        const __nv_bfloat16 (*bK)[KPAD] = sK[c & 1];

#pragma unroll
        for (int ks2 = 0; ks2 < 4; ks2++) {          // 16-key subgroup
            float Sacc[2][4];
            Sacc[0][0]=Sacc[0][1]=Sacc[0][2]=Sacc[0][3]=0.f;
            Sacc[1][0]=Sacc[1][1]=Sacc[1][2]=Sacc[1][3]=0.f;
#pragma unroll
            for (int ks = 0; ks < 4; ks++) {
                uint32_t f0,f1,f2,f3;
                ldmatrix_x4(f0,f1,f2,f3,
                    &bK[w2*64 + ks2*16 + (m>>1)*8 + r][ks*16 + (m&1)*8]);
                mma_bf16(Sacc[0], QA[ks], f0, f1);
                mma_bf16(Sacc[1], QA[ks], f2, f3);
            }
            rsum_lo += __expf(Sacc[0][0]) + __expf(Sacc[0][1])
                     + __expf(Sacc[1][0]) + __expf(Sacc[1][1]);
            rsum_hi += __expf(Sacc[0][2]) + __expf(Sacc[0][3])
                     + __expf(Sacc[1][2]) + __expf(Sacc[1][3]);
        }
        __syncthreads();
    }

    rsum_lo += __shfl_xor_sync(0xffffffffu, rsum_lo, 1);
    rsum_lo += __shfl_xor_sync(0xffffffffu, rsum_lo, 2);
    rsum_hi += __shfl_xor_sync(0xffffffffu, rsum_hi, 1);
    rsum_hi += __shfl_xor_sync(0xffffffffu, rsum_hi, 2);
    if (t == 0) {
        atomicAdd(&rs[qg][g],     rsum_lo);
        atomicAdd(&rs[qg][g + 8], rsum_hi);
    }
    __syncthreads();
    if (tid < 64) {
        int qq = tid >> 4, rr = tid & 15;
        g_rinv[(size_t)bh * SEQ + q0 + qq * 16 + rr] = 1.f / rs[qq][rr];
    }
}

// ---------------------------------------------------------------------------
// kernel 4: single-pass attention using precomputed 1/rowsum
//   per 16-key subgroup: recompute S (8 mma), P = exp(S)*rinv,
//   attn' = (1-P)/1023 streamed out, O += P V (8 mma)
// ---------------------------------------------------------------------------
#define ATTN_SMEM (4 * CHUNK * KPAD * 2)   // sK[2] + sV[2] = 73728 B

__global__ __launch_bounds__(256, 2)
void attn2_kernel(const float* __restrict__ q,
                  float* __restrict__ out,
                  float* __restrict__ attn) {
    extern __shared__ __align__(16) char dynsmem[];
    __nv_bfloat16 (*sK)[CHUNK][KPAD] =
        reinterpret_cast<__nv_bfloat16 (*)[CHUNK][KPAD]>(dynsmem);
    __nv_bfloat16 (*sV)[CHUNK][KPAD] =
        reinterpret_cast<__nv_bfloat16 (*)[CHUNK][KPAD]>(dynsmem + 2 * CHUNK * KPAD * 2);

    const int bh  = blockIdx.y;
    const int q0  = blockIdx.x * TILE_Q;
    const int tid = threadIdx.x;
    const int warp = tid >> 5, lane = tid & 31;
    const int qg = warp >> 1, w2 = warp & 1;
    const int g  = lane >> 2, t = lane & 3;
    const int m  = lane >> 3, r = lane & 7;

    const int row_lo = q0 + qg * 16 + g;
    uint32_t QA[4][4];
    load_q_frags(q + ((size_t)bh * SEQ + row_lo) * HD, QA, t);

    const float inv_lo = __ldg(&g_rinv[(size_t)bh * SEQ + row_lo]);
    const float inv_hi = __ldg(&g_rinv[(size_t)bh * SEQ + row_lo + 8]);

    const __nv_bfloat16* Kbh = g_kb + (size_t)bh * SEQ * HD;
    const __nv_bfloat16* Vbh = g_vb + (size_t)bh * SEQ * HD;

    float Oacc[8][4];
#pragma unroll
    for (int nt = 0; nt < 8; nt++)
        Oacc[nt][0] = Oacc[nt][1] = Oacc[nt][2] = Oacc[nt][3] = 0.f;

    float* attn_lo = attn + ((size_t)bh * SEQ + row_lo) * SEQ;
    float* attn_hi = attn_lo + (size_t)8 * SEQ;

    load_chunk(Kbh, &sK[0][0][0], tid);
    load_chunk(Vbh, &sV[0][0][0], tid);
    __pipeline_commit();
#pragma unroll 2
    for (int c = 0; c < NCHUNK; c++) {
        if (c + 1 < NCHUNK) {
            load_chunk(Kbh + (size_t)(c + 1) * CHUNK * HD, &sK[(c + 1) & 1][0][0], tid);
            load_chunk(Vbh + (size_t)(c + 1) * CHUNK * HD, &sV[(c + 1) & 1][0][0], tid);
            __pipeline_commit();
            __pipeline_wait_prior(1);
        } else {
            __pipeline_wait_prior(0);
        }
        __syncthreads();
        const __nv_bfloat16 (*bK)[KPAD] = sK[c & 1];
        const __nv_bfloat16 (*bV)[KPAD] = sV[c & 1];

#pragma unroll
        for (int ks2 = 0; ks2 < 4; ks2++) {          // 16-key subgroup
            // ---- recompute S for these 16 keys ----
            float Sacc[2][4];
            Sacc[0][0]=Sacc[0][1]=Sacc[0][2]=Sacc[0][3]=0.f;
            Sacc[1][0]=Sacc[1][1]=Sacc[1][2]=Sacc[1][3]=0.f;
#pragma unroll
            for (int ks = 0; ks < 4; ks++) {
                uint32_t f0,f1,f2,f3;
                ldmatrix_x4(f0,f1,f2,f3,
                    &bK[w2*64 + ks2*16 + (m>>1)*8 + r][ks*16 + (m&1)*8]);
                mma_bf16(Sacc[0], QA[ks], f0, f1);
                mma_bf16(Sacc[1], QA[ks], f2, f3);
            }
            // ---- P = exp(S) * rinv ----
            float p00 = __expf(Sacc[0][0]) * inv_lo, p01 = __expf(Sacc[0][1]) * inv_lo;
            float p10 = __expf(Sacc[0][2]) * inv_hi, p11 = __expf(Sacc[0][3]) * inv_hi;
            float p20 = __expf(Sacc[1][0]) * inv_lo, p21 = __expf(Sacc[1][1]) * inv_lo;
            float p30 = __expf(Sacc[1][2]) * inv_hi, p31 = __expf(Sacc[1][3]) * inv_hi;

            uint32_t aa[4];
            aa[0] = packbf(p00, p01);
            aa[1] = packbf(p10, p11);
            aa[2] = packbf(p20, p21);
            aa[3] = packbf(p30, p31);

            // ---- streaming attn stores: attn' = (1 - P)/1023 ----
            int kb = c * CHUNK + w2 * 64 + ks2 * 16;
            __stcs(reinterpret_cast<float2*>(attn_lo + kb + 2 * t),
                   make_float2((1.f - p00) * INV_DM1, (1.f - p01) * INV_DM1));
            __stcs(reinterpret_cast<float2*>(attn_hi + kb + 2 * t),
                   make_float2((1.f - p10) * INV_DM1, (1.f - p11) * INV_DM1));
            __stcs(reinterpret_cast<float2*>(attn_lo + kb + 8 + 2 * t),
                   make_float2((1.f - p20) * INV_DM1, (1.f - p21) * INV_DM1));
            __stcs(reinterpret_cast<float2*>(attn_hi + kb + 8 + 2 * t),
                   make_float2((1.f - p30) * INV_DM1, (1.f - p31) * INV_DM1));

            // ---- O += P V ----
            int vrow_base = w2 * 64 + ks2 * 16;
            int quad = lane >> 3, rq = lane & 7;
#pragma unroll
            for (int dp = 0; dp < 4; dp++) {
                uint32_t b0, b1, b2, b3;
                ldmatrix_x4_trans(b0, b1, b2, b3,
                    &bV[vrow_base + (quad & 1) * 8 + rq][dp * 16 + (quad >> 1) * 8]);
                mma_bf16(Oacc[2 * dp],     aa, b0, b1);
                mma_bf16(Oacc[2 * dp + 1], aa, b2, b3);
            }
        }
        __syncthreads();
    }

    // ---- epilogue: reduce O across warp pairs, out = (vsum - O)/1023 ----
    float (*Ored)[HD] = reinterpret_cast<float (*)[HD]>(dynsmem);   // 16 KB overlay
    if (w2 == 0) {
#pragma unroll
        for (int nt = 0; nt < 8; nt++) {
            *reinterpret_cast<float2*>(&Ored[qg * 16 + g][nt * 8 + 2 * t]) =
                make_float2(Oacc[nt][0], Oacc[nt][1]);
            *reinterpret_cast<float2*>(&Ored[qg * 16 + g + 8][nt * 8 + 2 * t]) =
                make_float2(Oacc[nt][2], Oacc[nt][3]);
        }
    }
    __syncthreads();
    if (w2 == 1) {
#pragma unroll
        for (int nt = 0; nt < 8; nt++) {
            float2* p0 = reinterpret_cast<float2*>(&Ored[qg * 16 + g][nt * 8 + 2 * t]);
            float2 v0 = *p0;
            v0.x += Oacc[nt][0]; v0.y += Oacc[nt][1];
            *p0 = v0;
            float2* p1 = reinterpret_cast<float2*>(&Ored[qg * 16 + g + 8][nt * 8 + 2 * t]);
            float2 v1 = *p1;
            v1.x += Oacc[nt][2]; v1.y += Oacc[nt][3];
            *p1 = v1;
        }
    }
    __syncthreads();

    float* outb = out + ((size_t)bh * SEQ + q0) * HD;
    for (int idx = tid; idx < TILE_Q * HD; idx += 256) {
        int rr = idx >> 6, d = idx & 63;
        outb[rr * HD + d] = (g_vsum[bh * HD + d] - Ored[rr][d]) * INV_DM1;
    }
}

// ---------------------------------------------------------------------------
// launch
// ---------------------------------------------------------------------------
extern "C" void kernel_launch(void* const* d_in, const int* in_sizes, int n_in,
                              void* d_out, int out_size) {
    (void)in_sizes; (void)n_in; (void)out_size;
    const float* q = (const float*)d_in[0];
    const float* k = (const float*)d_in[1];
    const float* v = (const float*)d_in[2];
    float* out  = (float*)d_out;
    float* attn = out + (size_t)BH * SEQ * HD;   // tuple order: (out, attn)

    // opt-in to >48KB dynamic smem (attribute set is idempotent & capture-safe)
    cudaFuncSetAttribute(attn2_kernel,
                         cudaFuncAttributeMaxDynamicSharedMemorySize, ATTN_SMEM);

    const int n4_total = 2 * (BH * SEQ * HD / 4);
    convert_kernel<<<n4_total / 256, 256>>>(k, v);
    vsum_kernel<<<BH, 256>>>(v);
    rowsum_kernel<<<dim3(SEQ / TILE_Q, BH), 256>>>(q);
    attn2_kernel<<<dim3(SEQ / TILE_Q, BH), 256, ATTN_SMEM>>>(q, out, attn);
}

// round 5
// speedup vs baseline: 1.6158x; 1.0347x over previous
#include <cuda_runtime.h>
#include <cuda_bf16.h>
#include <cuda_pipeline.h>
#include <cstdint>

// Problem constants
#define BH      128          // batch*heads
#define SEQ     1024
#define HD      64
#define TILE_Q  64           // query rows per block
#define CHUNK   128          // keys per smem chunk
#define NCHUNK  8            // SEQ / CHUNK
#define KPAD    72           // padded halves per smem row (conflict-free: 144B stride)
#define INV_TEMP 0.125f      // 1 / 8.0
#define INV_DM1  (1.0f/1023.0f)

// Device scratch (sanctioned no-alloc workaround).
__device__ __align__(256) __nv_bfloat16 g_kb[(size_t)BH * SEQ * HD];
__device__ __align__(256) __nv_bfloat16 g_vb[(size_t)BH * SEQ * HD];
__device__ __align__(256) float         g_vsum[BH * HD];
// E = exp(scores) spill buffer, bf16, stored in mma-fragment order (268 MB)
__device__ __align__(256) __nv_bfloat16 g_eb[(size_t)BH * SEQ * SEQ];

// ---------------------------------------------------------------------------
// helpers
// ---------------------------------------------------------------------------
__device__ __forceinline__ uint32_t packbf(float x, float y) {
    __nv_bfloat162 h = __floats2bfloat162_rn(x, y);
    return *reinterpret_cast<uint32_t*>(&h);
}

__device__ __forceinline__ float2 unpackbf(uint32_t r) {
    __nv_bfloat162 h = *reinterpret_cast<__nv_bfloat162*>(&r);
    return __bfloat1622float2(h);
}

// mma.sync m16n8k16 row.col f32 += bf16 * bf16
__device__ __forceinline__ void mma_bf16(float (&d)[4], const uint32_t (&a)[4],
                                         uint32_t b0, uint32_t b1) {
    asm volatile(
        "mma.sync.aligned.m16n8k16.row.col.f32.bf16.bf16.f32 "
        "{%0,%1,%2,%3},{%4,%5,%6,%7},{%8,%9},{%0,%1,%2,%3};"
        : "+f"(d[0]), "+f"(d[1]), "+f"(d[2]), "+f"(d[3])
        : "r"(a[0]), "r"(a[1]), "r"(a[2]), "r"(a[3]), "r"(b0), "r"(b1));
}

__device__ __forceinline__ void ldmatrix_x4(uint32_t& r0, uint32_t& r1,
                                            uint32_t& r2, uint32_t& r3,
                                            const void* p) {
    uint32_t sa = (uint32_t)__cvta_generic_to_shared(p);
    asm volatile("ldmatrix.sync.aligned.m8n8.x4.shared.b16 {%0,%1,%2,%3},[%4];"
                 : "=r"(r0), "=r"(r1), "=r"(r2), "=r"(r3) : "r"(sa));
}

__device__ __forceinline__ void ldmatrix_x4_trans(uint32_t& r0, uint32_t& r1,
                                                  uint32_t& r2, uint32_t& r3,
                                                  const void* p) {
    uint32_t sa = (uint32_t)__cvta_generic_to_shared(p);
    asm volatile("ldmatrix.sync.aligned.m8n8.x4.trans.shared.b16 {%0,%1,%2,%3},[%4];"
                 : "=r"(r0), "=r"(r1), "=r"(r2), "=r"(r3) : "r"(sa));
}

// cooperative async copy of one 128-key x 64-half chunk into padded smem
__device__ __forceinline__ void load_chunk(const __nv_bfloat16* __restrict__ src,
                                           __nv_bfloat16* dstbase, int tid) {
#pragma unroll
    for (int i = 0; i < 4; i++) {
        int gi  = tid + i * 256;
        int row = gi >> 3;      // 0..127
        int c16 = gi & 7;       // 16B segment within row
        __pipeline_memcpy_async(dstbase + row * KPAD + c16 * 8,
                                src + row * HD + c16 * 8, 16);
    }
}

// Q a-fragments: 16 rows per query-group, scaled by 1/8, packed bf16
__device__ __forceinline__ void load_q_frags(const float* __restrict__ qp,
                                             uint32_t (&QA)[4][4], int t) {
#pragma unroll
    for (int ks = 0; ks < 4; ks++) {
        float2 x0 = *reinterpret_cast<const float2*>(qp +          ks * 16 +     2 * t);
        float2 x1 = *reinterpret_cast<const float2*>(qp + 8 * HD + ks * 16 +     2 * t);
        float2 x2 = *reinterpret_cast<const float2*>(qp +          ks * 16 + 8 + 2 * t);
        float2 x3 = *reinterpret_cast<const float2*>(qp + 8 * HD + ks * 16 + 8 + 2 * t);
        QA[ks][0] = packbf(x0.x * INV_TEMP, x0.y * INV_TEMP);
        QA[ks][1] = packbf(x1.x * INV_TEMP, x1.y * INV_TEMP);
        QA[ks][2] = packbf(x2.x * INV_TEMP, x2.y * INV_TEMP);
        QA[ks][3] = packbf(x3.x * INV_TEMP, x3.y * INV_TEMP);
    }
}

// ---------------------------------------------------------------------------
// kernel 1: fp32 -> bf16 conversion of K and V
// ---------------------------------------------------------------------------
__global__ void convert_kernel(const float* __restrict__ k, const float* __restrict__ v) {
    const unsigned N4 = (unsigned)(BH * SEQ * HD / 4);
    unsigned i = blockIdx.x * blockDim.x + threadIdx.x;
    const float4* src;
    uint2* dst;
    if (i < N4) {
        src = reinterpret_cast<const float4*>(k) + i;
        dst = reinterpret_cast<uint2*>(g_kb) + i;
    } else {
        unsigned j = i - N4;
        src = reinterpret_cast<const float4*>(v) + j;
        dst = reinterpret_cast<uint2*>(g_vb) + j;
    }
    float4 x = *src;
    uint2 o;
    o.x = packbf(x.x, x.y);
    o.y = packbf(x.z, x.w);
    *dst = o;
}

// ---------------------------------------------------------------------------
// kernel 2: column sums of V per (b,h)  (fp32 source for precision)
// ---------------------------------------------------------------------------
__global__ void vsum_kernel(const float* __restrict__ v) {
    __shared__ float part[4][HD];
    int bh = blockIdx.x;
    int tid = threadIdx.x;                 // 256
    int d = tid & 63, seg = tid >> 6;      // 4 segments of 256 keys
    const float* p = v + (size_t)bh * SEQ * HD + (size_t)seg * 256 * HD + d;
    float s = 0.f;
#pragma unroll 8
    for (int k = 0; k < 256; k++) s += p[k * HD];
    part[seg][d] = s;
    __syncthreads();
    if (tid < HD)
        g_vsum[bh * HD + tid] = part[0][tid] + part[1][tid] + part[2][tid] + part[3][tid];
}

// ---------------------------------------------------------------------------
// kernel 3: fused attention, E spilled to global scratch
//   pass 1: S = (Q/8)K^T, E = exp(S) -> g_eb (fragment layout), rowsums
//   pass 2: reload E, attn' = (1 - E*rinv)/1023, O += E V; epilogue scales by rinv
// ---------------------------------------------------------------------------
__global__ __launch_bounds__(256, 2)
void fused_attn_kernel(const float* __restrict__ q,
                       float* __restrict__ out,
                       float* __restrict__ attn) {
    __shared__ __align__(16) __nv_bfloat16 sKV[2][CHUNK][KPAD];   // 36.9 KB
    __shared__ float rs[4][16];

    const int bh  = blockIdx.y;
    const int q0  = blockIdx.x * TILE_Q;
    const int tid = threadIdx.x;
    const int warp = tid >> 5, lane = tid & 31;
    const int qg = warp >> 1, w2 = warp & 1;
    const int g  = lane >> 2, t = lane & 3;
    const int m  = lane >> 3, r = lane & 7;

    if (tid < 64) ((float*)rs)[tid] = 0.f;

    const int row_lo = q0 + qg * 16 + g;
    uint32_t QA[4][4];
    load_q_frags(q + ((size_t)bh * SEQ + row_lo) * HD, QA, t);

    const __nv_bfloat16* Kbh = g_kb + (size_t)bh * SEQ * HD;
    const __nv_bfloat16* Vbh = g_vb + (size_t)bh * SEQ * HD;
    // per-CTA E region: 64 q-rows x 1024 keys x bf16 = 128 KB = 8192 uint4
    uint4* ep = reinterpret_cast<uint4*>(g_eb) +
                (((size_t)bh * 16 + blockIdx.x) << 13);

    float rsum_lo = 0.f, rsum_hi = 0.f;

    // ======================= pass 1: QK^T + exp -> E =======================
    load_chunk(Kbh, &sKV[0][0][0], tid);
    __pipeline_commit();
#pragma unroll 2
    for (int c = 0; c < NCHUNK; c++) {
        if (c + 1 < NCHUNK) {
            load_chunk(Kbh + (size_t)(c + 1) * CHUNK * HD, &sKV[(c + 1) & 1][0][0], tid);
            __pipeline_commit();
            __pipeline_wait_prior(1);
        } else {
            __pipeline_wait_prior(0);
        }
        __syncthreads();
        const __nv_bfloat16 (*bK)[KPAD] = sKV[c & 1];

#pragma unroll
        for (int ks2 = 0; ks2 < 4; ks2++) {
            float Sacc[2][4];
            Sacc[0][0]=Sacc[0][1]=Sacc[0][2]=Sacc[0][3]=0.f;
            Sacc[1][0]=Sacc[1][1]=Sacc[1][2]=Sacc[1][3]=0.f;
#pragma unroll
            for (int ks = 0; ks < 4; ks++) {
                uint32_t f0,f1,f2,f3;
                ldmatrix_x4(f0,f1,f2,f3,
                    &bK[w2*64 + ks2*16 + (m>>1)*8 + r][ks*16 + (m&1)*8]);
                mma_bf16(Sacc[0], QA[ks], f0, f1);
                mma_bf16(Sacc[1], QA[ks], f2, f3);
            }
            float e00 = __expf(Sacc[0][0]), e01 = __expf(Sacc[0][1]);
            float e02 = __expf(Sacc[0][2]), e03 = __expf(Sacc[0][3]);
            float e10 = __expf(Sacc[1][0]), e11 = __expf(Sacc[1][1]);
            float e12 = __expf(Sacc[1][2]), e13 = __expf(Sacc[1][3]);
            rsum_lo += e00 + e01 + e10 + e11;   // rows g
            rsum_hi += e02 + e03 + e12 + e13;   // rows g+8
            uint4 ev;
            ev.x = packbf(e00, e01);   // row g,   keys 2t..
            ev.y = packbf(e02, e03);   // row g+8, keys 2t..
            ev.z = packbf(e10, e11);   // row g,   keys 8+2t..
            ev.w = packbf(e12, e13);   // row g+8, keys 8+2t..
            ep[c * 1024 + warp * 128 + ks2 * 32 + lane] = ev;  // default: stays in L2
        }
        __syncthreads();
    }

    // prefetch first V chunk while we reduce rowsums
    load_chunk(Vbh, &sKV[0][0][0], tid);
    __pipeline_commit();

    // ---- row-sum reduction ----
    rsum_lo += __shfl_xor_sync(0xffffffffu, rsum_lo, 1);
    rsum_lo += __shfl_xor_sync(0xffffffffu, rsum_lo, 2);
    rsum_hi += __shfl_xor_sync(0xffffffffu, rsum_hi, 1);
    rsum_hi += __shfl_xor_sync(0xffffffffu, rsum_hi, 2);
    if (t == 0) {
        atomicAdd(&rs[qg][g],     rsum_lo);
        atomicAdd(&rs[qg][g + 8], rsum_hi);
    }
    __syncthreads();
    const float inv_lo = 1.f / rs[qg][g];
    const float inv_hi = 1.f / rs[qg][g + 8];

    // ======================= pass 2: attn' + O += E V =======================
    float Oacc[8][4];
#pragma unroll
    for (int nt = 0; nt < 8; nt++)
        Oacc[nt][0] = Oacc[nt][1] = Oacc[nt][2] = Oacc[nt][3] = 0.f;

    float* attn_lo = attn + ((size_t)bh * SEQ + row_lo) * SEQ;
    float* attn_hi = attn_lo + (size_t)8 * SEQ;

#pragma unroll 2
    for (int c = 0; c < NCHUNK; c++) {
        if (c + 1 < NCHUNK) {
            load_chunk(Vbh + (size_t)(c + 1) * CHUNK * HD, &sKV[(c + 1) & 1][0][0], tid);
            __pipeline_commit();
            __pipeline_wait_prior(1);
        } else {
            __pipeline_wait_prior(0);
        }
        __syncthreads();
        const __nv_bfloat16 (*bV)[KPAD] = sKV[c & 1];

#pragma unroll
        for (int ks2 = 0; ks2 < 4; ks2++) {
            uint4 ev = ep[c * 1024 + warp * 128 + ks2 * 32 + lane];

            // attn' = (1 - E*rinv)/1023
            float2 eA = unpackbf(ev.x);
            float2 eB = unpackbf(ev.y);
            float2 eC = unpackbf(ev.z);
            float2 eD = unpackbf(ev.w);
            int kb = c * CHUNK + w2 * 64 + ks2 * 16;
            __stcs(reinterpret_cast<float2*>(attn_lo + kb + 2 * t),
                   make_float2((1.f - eA.x * inv_lo) * INV_DM1,
                               (1.f - eA.y * inv_lo) * INV_DM1));
            __stcs(reinterpret_cast<float2*>(attn_hi + kb + 2 * t),
                   make_float2((1.f - eB.x * inv_hi) * INV_DM1,
                               (1.f - eB.y * inv_hi) * INV_DM1));
            __stcs(reinterpret_cast<float2*>(attn_lo + kb + 8 + 2 * t),
                   make_float2((1.f - eC.x * inv_lo) * INV_DM1,
                               (1.f - eC.y * inv_lo) * INV_DM1));
            __stcs(reinterpret_cast<float2*>(attn_hi + kb + 8 + 2 * t),
                   make_float2((1.f - eD.x * inv_hi) * INV_DM1,
                               (1.f - eD.y * inv_hi) * INV_DM1));

            // O += E V  (rinv folded into epilogue)
            uint32_t aa[4] = {ev.x, ev.y, ev.z, ev.w};
            int vrow_base = w2 * 64 + ks2 * 16;
            int quad = lane >> 3, rq = lane & 7;
#pragma unroll
            for (int dp = 0; dp < 4; dp++) {
                uint32_t b0, b1, b2, b3;
                ldmatrix_x4_trans(b0, b1, b2, b3,
                    &bV[vrow_base + (quad & 1) * 8 + rq][dp * 16 + (quad >> 1) * 8]);
                mma_bf16(Oacc[2 * dp],     aa, b0, b1);
                mma_bf16(Oacc[2 * dp + 1], aa, b2, b3);
            }
        }
        __syncthreads();
    }

    // ---- epilogue: scale by rinv, reduce across warp pairs, write out ----
#pragma unroll
    for (int nt = 0; nt < 8; nt++) {
        Oacc[nt][0] *= inv_lo; Oacc[nt][1] *= inv_lo;   // row g
        Oacc[nt][2] *= inv_hi; Oacc[nt][3] *= inv_hi;   // row g+8
    }

    float (*Ored)[HD] = reinterpret_cast<float (*)[HD]>(&sKV[0][0][0]);  // 16 KB overlay
    if (w2 == 0) {
#pragma unroll
        for (int nt = 0; nt < 8; nt++) {
            *reinterpret_cast<float2*>(&Ored[qg * 16 + g][nt * 8 + 2 * t]) =
                make_float2(Oacc[nt][0], Oacc[nt][1]);
            *reinterpret_cast<float2*>(&Ored[qg * 16 + g + 8][nt * 8 + 2 * t]) =
                make_float2(Oacc[nt][2], Oacc[nt][3]);
        }
    }
    __syncthreads();
    if (w2 == 1) {
#pragma unroll
        for (int nt = 0; nt < 8; nt++) {
            float2* p0 = reinterpret_cast<float2*>(&Ored[qg * 16 + g][nt * 8 + 2 * t]);
            float2 v0 = *p0;
            v0.x += Oacc[nt][0]; v0.y += Oacc[nt][1];
            *p0 = v0;
            float2* p1 = reinterpret_cast<float2*>(&Ored[qg * 16 + g + 8][nt * 8 + 2 * t]);
            float2 v1 = *p1;
            v1.x += Oacc[nt][2]; v1.y += Oacc[nt][3];
            *p1 = v1;
        }
    }
    __syncthreads();

    float* outb = out + ((size_t)bh * SEQ + q0) * HD;
    for (int idx = tid; idx < TILE_Q * HD; idx += 256) {
        int rr = idx >> 6, d = idx & 63;
        outb[rr * HD + d] = (g_vsum[bh * HD + d] - Ored[rr][d]) * INV_DM1;
    }
}

// ---------------------------------------------------------------------------
// launch
// ---------------------------------------------------------------------------
extern "C" void kernel_launch(void* const* d_in, const int* in_sizes, int n_in,
                              void* d_out, int out_size) {
    (void)in_sizes; (void)n_in; (void)out_size;
    const float* q = (const float*)d_in[0];
    const float* k = (const float*)d_in[1];
    const float* v = (const float*)d_in[2];
    float* out  = (float*)d_out;
    float* attn = out + (size_t)BH * SEQ * HD;   // tuple order: (out, attn)

    const int n4_total = 2 * (BH * SEQ * HD / 4);
    convert_kernel<<<n4_total / 256, 256>>>(k, v);
    vsum_kernel<<<BH, 256>>>(v);
    fused_attn_kernel<<<dim3(SEQ / TILE_Q, BH), 256>>>(q, out, attn);
}